// round 10
// baseline (speedup 1.0000x reference)
#include <cuda_runtime.h>
#include <cuda_fp16.h>
#include <cstdint>
#include <cstddef>

// Problem constants (B=64,T=2048,D=128,K=1024)
#define Dm     128
#define Kc     1024
#define TM     64              // tokens per CTA
#define TN     32              // codes per tile
#define NTILES 32
#define DECAYF 0.99f
#define OMDEC  0.01f
#define EPSV   1e-5f

// ---- device scratch (no allocations allowed) ----
__device__ float    g_esum[Kc * Dm];
__device__ float    g_counts[Kc];
__device__ float    g_enorm[Kc];
__device__ float    g_smooth[Kc];
// embed pre-split into 3 fp16 planes, fragment-ordered per 32-code tile:
// [tile32][plane3][2048 uints]
__device__ unsigned g_bsplit[NTILES * 3 * 2048];

// ------------------------------------------------------------------
// helpers
// ------------------------------------------------------------------
__device__ __forceinline__ uint32_t smem_u32(const void* p) {
    uint32_t a;
    asm("{ .reg .u64 t; cvta.to.shared.u64 t, %1; cvt.u32.u64 %0, t; }"
        : "=r"(a) : "l"(p));
    return a;
}
__device__ __forceinline__ void split3(float v, __half& a, __half& b, __half& c) {
    a = __float2half_rn(v);
    float r = v - __half2float(a);
    b = __float2half_rn(r);
    float r2 = r - __half2float(b);
    c = __float2half_rn(r2);
}
__device__ __forceinline__ unsigned packh(__half lo, __half hi) {
    return ((unsigned)__half_as_ushort(hi) << 16) | (unsigned)__half_as_ushort(lo);
}

#define CP_ASYNC16(dst, src) \
    asm volatile("cp.async.cg.shared.global [%0], [%1], 16;" \
                 :: "r"(dst), "l"(src) : "memory")
#define CP_COMMIT() asm volatile("cp.async.commit_group;" ::: "memory")
#define CP_WAIT0()  asm volatile("cp.async.wait_group 0;" ::: "memory")

// m16n8k16 fp16 mma, fp32 accumulate (sm_80 baseline PTX — compiles at compute_103)
#define MMA(acc, av, bv) \
    asm volatile("mma.sync.aligned.m16n8k16.row.col.f32.f16.f16.f32 " \
        "{%0,%1,%2,%3},{%4,%5,%6,%7},{%8,%9},{%0,%1,%2,%3};" \
        : "+f"((acc)[0]), "+f"((acc)[1]), "+f"((acc)[2]), "+f"((acc)[3]) \
        : "r"((av).x), "r"((av).y), "r"((av).z), "r"((av).w), \
          "r"((bv).x), "r"((bv).y))

// ------------------------------------------------------------------
// smem layout (bytes), per CTA (~98.5 KB => 2 CTAs/SM)
//   A frags:  3 planes x 4096 uints = 49152
//   B bufs:   2 x (6144 uints frag + 32 floats enorm) = 2 x 24704
//   red:      redV f32[64][4] | redK i32[64][4] | sidx i32[64]
// ------------------------------------------------------------------
#define OFF_B0   49152
#define BUFSTR   24704
#define OFF_RED  (OFF_B0 + 2 * BUFSTR)                    // 98560
#define SMEM_TOTAL (OFF_RED + 1024 + 1024 + 256)          // 100864

// ------------------------------------------------------------------
// zero the scatter accumulators (graph is replayed; must re-zero)
// ------------------------------------------------------------------
__global__ void init_kernel() {
    int i = blockIdx.x * blockDim.x + threadIdx.x;
    if (i < Kc * Dm) g_esum[i] = 0.0f;
    if (i < Kc)      g_counts[i] = 0.0f;
}

// ------------------------------------------------------------------
// per-code 0.5*||e||^2
// ------------------------------------------------------------------
__global__ void enorm_kernel(const float* __restrict__ embed) {
    int gtid = blockIdx.x * blockDim.x + threadIdx.x;
    int warp = gtid >> 5;
    int lane = gtid & 31;
    if (warp >= Kc) return;
    float4 v = *reinterpret_cast<const float4*>(embed + (size_t)warp * Dm + lane * 4);
    float s = v.x * v.x + v.y * v.y + v.z * v.z + v.w * v.w;
    #pragma unroll
    for (int o = 16; o > 0; o >>= 1) s += __shfl_xor_sync(0xffffffffu, s, o);
    if (lane == 0) g_enorm[warp] = 0.5f * s;
}

// ------------------------------------------------------------------
// embed 3-way fp16 split, fragment-ordered (B frag of m16n8k16 .col):
// b-reg for (n,k): lane=(n&7)*4+((k>>1)&3), reg=(k>>3)&1, half=k&1
// tile = 32 codes; frag (ng 0..3, s 0..7) = 64 uints
// ------------------------------------------------------------------
__global__ void prep_e_kernel(const float* __restrict__ embed) {
    int u = blockIdx.x * blockDim.x + threadIdx.x;   // (n, k-pair)
    if (u >= Kc * 64) return;
    int n = u >> 6, j = u & 63;
    float2 v = *reinterpret_cast<const float2*>(embed + (size_t)n * Dm + 2 * j);
    __half a1, a2, a3, b1, b2, b3;
    split3(v.x, a1, a2, a3);
    split3(v.y, b1, b2, b3);
    int tile = n >> 5, nl = n & 31;
    int ng = nl >> 3, lrow = nl & 7;
    int s = j >> 3, reg = (j >> 2) & 1, lcol = j & 3;
    int ln = lrow * 4 + lcol;
    int base = tile * 6144 + (ng * 8 + s) * 64 + ln * 2 + reg;
    g_bsplit[base]        = packh(a1, b1);
    g_bsplit[base + 2048] = packh(a2, b2);
    g_bsplit[base + 4096] = packh(a3, b3);
}

// ------------------------------------------------------------------
// main: fp16 6-pass distance GEMM (mma.sync) + argmax + fused scatter
// dist = dot(x,e) - 0.5||e||^2 ;  dot = Σ_{(i,j) in 6 terms} h_i(x)·h_j(e)
// 8 warps: mg = wid&1 (32-row group), ng = wid>>1 (8-code group)
// ------------------------------------------------------------------
__global__ void __launch_bounds__(256, 2)
argmax_kernel(const float* __restrict__ x, const float* __restrict__ embed,
              float* __restrict__ outq, float* __restrict__ outind)
{
    extern __shared__ char smem[];
    const int tid  = threadIdx.x;
    const int wid  = tid >> 5;
    const int lane = tid & 31;
    const int mg   = wid & 1;            // 0..1  (32-token group)
    const int ng   = wid >> 1;           // 0..3  (8-code group)
    const int tok0 = blockIdx.x * TM;

    unsigned* Au  = reinterpret_cast<unsigned*>(smem);
    float* redV = reinterpret_cast<float*>(smem + OFF_RED);
    int*   redK = reinterpret_cast<int*>(smem + OFF_RED + 1024);
    int*   sidx = reinterpret_cast<int*>(smem + OFF_RED + 2048);

    // --- one-time A split: x[64][128] -> 3 fp16 planes in frag order ---
    for (int u = tid; u < TM * 64; u += 256) {
        int r = u >> 6, j = u & 63;
        float2 v = *reinterpret_cast<const float2*>(
            x + (size_t)(tok0 + r) * Dm + 2 * j);
        __half a1, a2, a3, b1, b2, b3;
        split3(v.x, a1, a2, a3);
        split3(v.y, b1, b2, b3);
        int mgr = r >> 5, mt = (r >> 4) & 1, rega = (r >> 3) & 1, lrow = r & 7;
        int s = j >> 3, regb = (j >> 2) & 1, lcol = j & 3;
        int ln = lrow * 4 + lcol, rg = regb * 2 + rega;
        int base = ((mgr * 8 + s) * 2 + mt) * 128 + ln * 4 + rg;
        Au[base]         = packh(a1, b1);
        Au[base + 4096]  = packh(a2, b2);
        Au[base + 8192]  = packh(a3, b3);
    }

    // --- prologue: cp.async B tile 0 (+ enorm) into buf0 ---
    {
        uint32_t dst = smem_u32(smem + OFF_B0);
        const uint4* src = reinterpret_cast<const uint4*>(g_bsplit);
        #pragma unroll
        for (int i = 0; i < 6; i++) {
            int idx = tid + i * 256;            // uint4 units, 1536 total
            CP_ASYNC16(dst + idx * 16, src + idx);
        }
        if (tid < 8)
            CP_ASYNC16(dst + 24576 + tid * 16,
                       reinterpret_cast<const char*>(g_enorm) + tid * 16);
        CP_COMMIT();
    }

    float best[4];
    int   bestk[4];
    #pragma unroll
    for (int i = 0; i < 4; i++) { best[i] = -3.4e38f; bestk[i] = 0; }

    for (int t = 0; t < NTILES; t++) {
        CP_WAIT0();
        __syncthreads();   // tile t resident; also covers A-split on t=0

        if (t + 1 < NTILES) {   // prefetch tile t+1 into the other buffer
            uint32_t dst = smem_u32(smem + OFF_B0 + ((t + 1) & 1) * BUFSTR);
            const uint4* src = reinterpret_cast<const uint4*>(
                g_bsplit + (size_t)(t + 1) * 6144);
            #pragma unroll
            for (int i = 0; i < 6; i++) {
                int idx = tid + i * 256;
                CP_ASYNC16(dst + idx * 16, src + idx);
            }
            if (tid < 8)
                CP_ASYNC16(dst + 24576 + tid * 16,
                           reinterpret_cast<const char*>(g_enorm + (t + 1) * TN) + tid * 16);
        }
        CP_COMMIT();

        const char* bufc = smem + OFF_B0 + (t & 1) * BUFSTR;
        const uint4* Af = reinterpret_cast<const uint4*>(smem);   // [plane][1024 uint4]
        const uint2* Bf = reinterpret_cast<const uint2*>(bufc);   // [plane][1024 uint2]
        const float* ens = reinterpret_cast<const float*>(bufc + 24576);

        float acc[2][4];
        #pragma unroll
        for (int mt = 0; mt < 2; mt++)
            #pragma unroll
            for (int q = 0; q < 4; q++) acc[mt][q] = 0.0f;

        #pragma unroll
        for (int s = 0; s < 8; s++) {
            uint4 a[3][2];
            uint2 b[3];
            #pragma unroll
            for (int p = 0; p < 3; p++) {
                #pragma unroll
                for (int mt = 0; mt < 2; mt++)
                    a[p][mt] = Af[p * 1024 + ((mg * 8 + s) * 2 + mt) * 32 + lane];
                b[p] = Bf[p * 1024 + (ng * 8 + s) * 32 + lane];
            }
            #pragma unroll
            for (int mt = 0; mt < 2; mt++) {
                MMA(acc[mt], a[0][mt], b[0]);   // h1*e1
                MMA(acc[mt], a[0][mt], b[1]);   // h1*e2
                MMA(acc[mt], a[1][mt], b[0]);   // h2*e1
                MMA(acc[mt], a[1][mt], b[1]);   // h2*e2
                MMA(acc[mt], a[0][mt], b[2]);   // h1*e3
                MMA(acc[mt], a[2][mt], b[0]);   // h3*e1
            }
        }

        // --- fold tile into running argmax (codes ascending => first-max) ---
        {
            int cl = ng * 8 + (lane & 3) * 2;
            float e0 = ens[cl], e1 = ens[cl + 1];
            int code0 = t * TN + cl;
            #pragma unroll
            for (int mt = 0; mt < 2; mt++) {
                int i0 = mt * 2, i1 = mt * 2 + 1;
                float d;
                d = acc[mt][0] - e0;
                if (d > best[i0]) { best[i0] = d; bestk[i0] = code0; }
                d = acc[mt][1] - e1;
                if (d > best[i0]) { best[i0] = d; bestk[i0] = code0 + 1; }
                d = acc[mt][2] - e0;
                if (d > best[i1]) { best[i1] = d; bestk[i1] = code0; }
                d = acc[mt][3] - e1;
                if (d > best[i1]) { best[i1] = d; bestk[i1] = code0 + 1; }
            }
        }
    }

    // --- reduce over the 4 col-lanes sharing each row ---
    #pragma unroll
    for (int off = 1; off <= 2; off <<= 1) {
        #pragma unroll
        for (int i = 0; i < 4; i++) {
            float ov = __shfl_xor_sync(0xffffffffu, best[i], off);
            int   ok = __shfl_xor_sync(0xffffffffu, bestk[i], off);
            if (ov > best[i] || (ov == best[i] && ok < bestk[i])) {
                best[i] = ov; bestk[i] = ok;
            }
        }
    }
    if ((lane & 3) == 0) {
        #pragma unroll
        for (int i = 0; i < 4; i++) {
            int R = mg * 32 + (i >> 1) * 16 + (i & 1) * 8 + (lane >> 2);
            redV[R * 4 + ng] = best[i];
            redK[R * 4 + ng] = bestk[i];
        }
    }
    __syncthreads();
    if (tid < TM) {
        float bv = redV[tid * 4];
        int   bk = redK[tid * 4];
        #pragma unroll
        for (int j = 1; j < 4; j++) {
            float v  = redV[tid * 4 + j];
            int   k2 = redK[tid * 4 + j];
            if (v > bv || (v == bv && k2 < bk)) { bv = v; bk = k2; }
        }
        sidx[tid] = bk;
        outind[tok0 + tid] = (float)bk;
        atomicAdd(&g_counts[bk], 1.0f);
    }
    __syncthreads();

    // --- fused epilogue: quantized gather + EMA scatter-adds ---
    for (int i = tid; i < TM * 32; i += 256) {
        int tt = i >> 5;
        int d4 = i & 31;
        int k  = sidx[tt];
        float4 ev = *reinterpret_cast<const float4*>(embed + (size_t)k * Dm + d4 * 4);
        *reinterpret_cast<float4*>(outq + (size_t)(tok0 + tt) * Dm + d4 * 4) = ev;
        float4 xv = *reinterpret_cast<const float4*>(x + (size_t)(tok0 + tt) * Dm + d4 * 4);
        float* es = g_esum + (size_t)k * Dm + d4 * 4;
        atomicAdd(es + 0, xv.x);
        atomicAdd(es + 1, xv.y);
        atomicAdd(es + 2, xv.z);
        atomicAdd(es + 3, xv.w);
    }
}

// ------------------------------------------------------------------
// finalize A: cluster-size EMA + laplace smoothing (1 block, K threads)
// ------------------------------------------------------------------
__global__ void __launch_bounds__(1024)
finalize_a(const float* __restrict__ cluster_size, float* __restrict__ out_ncs)
{
    __shared__ float ssum[32];
    __shared__ float s_total;
    int tid = threadIdx.x, lane = tid & 31;

    float ncs = cluster_size[tid] * DECAYF + OMDEC * g_counts[tid];
    out_ncs[tid] = ncs;

    float s = ncs;
    #pragma unroll
    for (int o = 16; o > 0; o >>= 1) s += __shfl_xor_sync(0xffffffffu, s, o);
    if (lane == 0) ssum[tid >> 5] = s;
    __syncthreads();
    if (tid < 32) {
        float v = ssum[tid];
        #pragma unroll
        for (int o = 16; o > 0; o >>= 1) v += __shfl_xor_sync(0xffffffffu, v, o);
        if (tid == 0) s_total = v;
    }
    __syncthreads();
    float total = s_total;
    g_smooth[tid] = (ncs + EPSV) / (total + (float)Kc * EPSV) * total;
}

// ------------------------------------------------------------------
// finalize B: embed_avg EMA + normalized embed (wide grid)
// ------------------------------------------------------------------
__global__ void finalize_b(const float* __restrict__ embed_avg,
                           float* __restrict__ out_ne,
                           float* __restrict__ out_nea)
{
    int i = blockIdx.x * blockDim.x + threadIdx.x;
    if (i >= Kc * Dm) return;
    float nea = embed_avg[i] * DECAYF + OMDEC * g_esum[i];
    out_nea[i] = nea;
    out_ne[i]  = nea / g_smooth[i >> 7];
}

// ------------------------------------------------------------------
// launch
// inputs: 0=x [N,128], 1=embed [1024,128], 2=embed_avg [1024,128],
//         3=cluster_size [1024]  (all f32)
// output (concat f32): quantized [N*128] | embed_ind [N] | new_embed [K*128]
//                    | new_cluster_size [K] | new_embed_avg [K*128]
// ------------------------------------------------------------------
extern "C" void kernel_launch(void* const* d_in, const int* in_sizes, int n_in,
                              void* d_out, int out_size)
{
    const float* x     = (const float*)d_in[0];
    const float* embed = (const float*)d_in[1];
    const float* eavg  = (const float*)d_in[2];
    const float* csz   = (const float*)d_in[3];
    float* out = (float*)d_out;

    int N = in_sizes[0] / Dm;

    size_t o_ind = (size_t)N * Dm;
    size_t o_ne  = o_ind + N;
    size_t o_ncs = o_ne + (size_t)Kc * Dm;
    size_t o_nea = o_ncs + Kc;

    cudaFuncSetAttribute(argmax_kernel,
                         cudaFuncAttributeMaxDynamicSharedMemorySize, SMEM_TOTAL);

    init_kernel<<<(Kc * Dm + 255) / 256, 256>>>();
    enorm_kernel<<<(Kc * 32 + 255) / 256, 256>>>(embed);
    prep_e_kernel<<<(Kc * 64 + 255) / 256, 256>>>(embed);
    argmax_kernel<<<N / TM, 256, SMEM_TOTAL>>>(x, embed, out, out + o_ind);
    finalize_a<<<1, 1024>>>(csz, out + o_ncs);
    finalize_b<<<(Kc * Dm + 255) / 256, 256>>>(eavg, out + o_ne, out + o_nea);
}

// round 14
// speedup vs baseline: 1.6524x; 1.6524x over previous
#include <cuda_runtime.h>
#include <cuda_fp16.h>
#include <cstdint>
#include <cstddef>

// Problem constants (B=64,T=2048,D=128,K=1024)
#define Dm     128
#define Kc     1024
#define TM     128             // tokens per CTA
#define TN     128             // codes per tile
#define NTILES 8
#define DECAYF 0.99f
#define OMDEC  0.01f
#define EPSV   1e-5f

// ---- device scratch (no allocations allowed) ----
__device__ float    g_esum[Kc * Dm];
__device__ float    g_counts[Kc];
__device__ float    g_enorm[Kc];
__device__ float    g_smooth[Kc];
// embed 2-way fp16 split, fragment-ordered: [tile8][plane2][8192 uints]
__device__ unsigned g_bsplit[NTILES * 2 * 8192];

// ------------------------------------------------------------------
// helpers
// ------------------------------------------------------------------
__device__ __forceinline__ uint32_t smem_u32(const void* p) {
    uint32_t a;
    asm("{ .reg .u64 t; cvta.to.shared.u64 t, %1; cvt.u32.u64 %0, t; }"
        : "=r"(a) : "l"(p));
    return a;
}
__device__ __forceinline__ void split2(float v, __half& a, __half& b) {
    a = __float2half_rn(v);
    b = __float2half_rn(v - __half2float(a));
}
__device__ __forceinline__ unsigned packh(__half lo, __half hi) {
    return ((unsigned)__half_as_ushort(hi) << 16) | (unsigned)__half_as_ushort(lo);
}

#define CP_ASYNC16(dst, src) \
    asm volatile("cp.async.cg.shared.global [%0], [%1], 16;" \
                 :: "r"(dst), "l"(src) : "memory")
#define CP_COMMIT() asm volatile("cp.async.commit_group;" ::: "memory")
#define CP_WAIT0()  asm volatile("cp.async.wait_group 0;" ::: "memory")

// m16n8k16 fp16 mma, fp32 accumulate (sm_80 baseline PTX — compiles at compute_103)
#define MMA(acc, av, bv) \
    asm volatile("mma.sync.aligned.m16n8k16.row.col.f32.f16.f16.f32 " \
        "{%0,%1,%2,%3},{%4,%5,%6,%7},{%8,%9},{%0,%1,%2,%3};" \
        : "+f"((acc)[0]), "+f"((acc)[1]), "+f"((acc)[2]), "+f"((acc)[3]) \
        : "r"((av).x), "r"((av).y), "r"((av).z), "r"((av).w), \
          "r"((bv).x), "r"((bv).y))

// ------------------------------------------------------------------
// smem layout (bytes) — 1 CTA/SM
//   A frags:  2 planes x 8192 uints = 65536
//   B bufs:   2 x (2 planes x 8192 uints + 128 floats enorm) = 2 x 66048
//   red:      redV f32[128][4] | redK i32[128][4] | sidx i32[128]
// ------------------------------------------------------------------
#define OFF_B0   65536
#define BUFSTR   66048
#define OFF_RED  (OFF_B0 + 2 * BUFSTR)                    // 197632
#define SMEM_TOTAL (OFF_RED + 2048 + 2048 + 512)          // 202240

// ------------------------------------------------------------------
// zero the scatter accumulators (graph is replayed; must re-zero)
// ------------------------------------------------------------------
__global__ void init_kernel() {
    int i = blockIdx.x * blockDim.x + threadIdx.x;
    if (i < Kc * Dm) g_esum[i] = 0.0f;
    if (i < Kc)      g_counts[i] = 0.0f;
}

// ------------------------------------------------------------------
// per-code 0.5*||e||^2
// ------------------------------------------------------------------
__global__ void enorm_kernel(const float* __restrict__ embed) {
    int gtid = blockIdx.x * blockDim.x + threadIdx.x;
    int warp = gtid >> 5;
    int lane = gtid & 31;
    if (warp >= Kc) return;
    float4 v = *reinterpret_cast<const float4*>(embed + (size_t)warp * Dm + lane * 4);
    float s = v.x * v.x + v.y * v.y + v.z * v.z + v.w * v.w;
    #pragma unroll
    for (int o = 16; o > 0; o >>= 1) s += __shfl_xor_sync(0xffffffffu, s, o);
    if (lane == 0) g_enorm[warp] = 0.5f * s;
}

// ------------------------------------------------------------------
// embed 2-way fp16 split, fragment-ordered (B frag of m16n8k16 .col):
// b-reg for (n,k): lane=(n&7)*4+((k>>1)&3), reg=(k>>3)&1, half=k&1
// tile = 128 codes; per plane: [ng4][s8][nt4][lane32] uint2 = 8192 uints
// ------------------------------------------------------------------
__global__ void prep_e_kernel(const float* __restrict__ embed) {
    int u = blockIdx.x * blockDim.x + threadIdx.x;   // (n, k-pair)
    if (u >= Kc * 64) return;
    int n = u >> 6, j = u & 63;
    float2 v = *reinterpret_cast<const float2*>(embed + (size_t)n * Dm + 2 * j);
    __half a1, a2, b1, b2;
    split2(v.x, a1, a2);
    split2(v.y, b1, b2);
    int tile = n >> 7, nl = n & 127;
    int ng = nl >> 5, nt = (nl >> 3) & 3, lrow = nl & 7;
    int s = j >> 3, reg = (j >> 2) & 1, lcol = j & 3;
    int ln = lrow * 4 + lcol;
    int base = tile * 16384 + (((ng * 8 + s) * 4 + nt) * 32 + ln) * 2 + reg;
    g_bsplit[base]        = packh(a1, b1);
    g_bsplit[base + 8192] = packh(a2, b2);
}

// ------------------------------------------------------------------
// main: fp16 3-pass distance GEMM (mma.sync) + argmax + fused scatter
// dist = dot(x,e) - 0.5||e||^2 ; dot = h1x·h1e + h1x·h2e + h2x·h1e
// (residual h2x·h2e ~ 2^-24 < fp32 accumulation noise — dropped)
// 8 warps: mg = wid>>2 (64-row group), ng = wid&3 (32-code group)
// ------------------------------------------------------------------
__global__ void __launch_bounds__(256, 1)
argmax_kernel(const float* __restrict__ x, const float* __restrict__ embed,
              float* __restrict__ outq, float* __restrict__ outind)
{
    extern __shared__ char smem[];
    const int tid  = threadIdx.x;
    const int wid  = tid >> 5;
    const int lane = tid & 31;
    const int mg   = wid >> 2;           // 0..1  (64-token group)
    const int ng   = wid & 3;            // 0..3  (32-code group)
    const int tok0 = blockIdx.x * TM;

    unsigned* Au  = reinterpret_cast<unsigned*>(smem);
    float* redV = reinterpret_cast<float*>(smem + OFF_RED);
    int*   redK = reinterpret_cast<int*>(smem + OFF_RED + 2048);
    int*   sidx = reinterpret_cast<int*>(smem + OFF_RED + 4096);

    // --- one-time A split: x[128][128] -> 2 fp16 planes in frag order ---
    // A plane layout: [mg2][s8][mt4][lane32] uint4 = 8192 uints
    for (int u = tid; u < TM * 64; u += 256) {
        int r = u >> 6, j = u & 63;
        float2 v = *reinterpret_cast<const float2*>(
            x + (size_t)(tok0 + r) * Dm + 2 * j);
        __half a1, a2, b1, b2;
        split2(v.x, a1, a2);
        split2(v.y, b1, b2);
        int mgr = r >> 6, mt = (r >> 4) & 3, rega = (r >> 3) & 1, lrow = r & 7;
        int s = j >> 3, regb = (j >> 2) & 1, lcol = j & 3;
        int ln = lrow * 4 + lcol, rg = regb * 2 + rega;
        int base = ((mgr * 8 + s) * 4 + mt) * 128 + ln * 4 + rg;
        Au[base]        = packh(a1, b1);
        Au[base + 8192] = packh(a2, b2);
    }

    // --- prologue: cp.async B tile 0 (+ enorm) into buf0 ---
    {
        uint32_t dst = smem_u32(smem + OFF_B0);
        const uint4* src = reinterpret_cast<const uint4*>(g_bsplit);
        #pragma unroll
        for (int i = 0; i < 16; i++) {
            int idx = tid + i * 256;            // uint4 units, 4096 total
            CP_ASYNC16(dst + idx * 16, src + idx);
        }
        if (tid < 32)
            CP_ASYNC16(dst + 65536 + tid * 16,
                       reinterpret_cast<const char*>(g_enorm) + tid * 16);
        CP_COMMIT();
    }

    float best[8];
    int   bestk[8];
    #pragma unroll
    for (int i = 0; i < 8; i++) { best[i] = -3.4e38f; bestk[i] = 0; }

    for (int t = 0; t < NTILES; t++) {
        CP_WAIT0();
        __syncthreads();   // tile t resident; also covers A-split on t=0

        if (t + 1 < NTILES) {   // prefetch tile t+1 into the other buffer
            uint32_t dst = smem_u32(smem + OFF_B0 + ((t + 1) & 1) * BUFSTR);
            const uint4* src = reinterpret_cast<const uint4*>(
                g_bsplit + (size_t)(t + 1) * 16384);
            #pragma unroll
            for (int i = 0; i < 16; i++) {
                int idx = tid + i * 256;
                CP_ASYNC16(dst + idx * 16, src + idx);
            }
            if (tid < 32)
                CP_ASYNC16(dst + 65536 + tid * 16,
                           reinterpret_cast<const char*>(g_enorm + (t + 1) * TN) + tid * 16);
        }
        CP_COMMIT();

        const char* bufc = smem + OFF_B0 + (t & 1) * BUFSTR;
        const uint4* Af = reinterpret_cast<const uint4*>(smem);   // [plane][2048 uint4]
        const uint2* Bf = reinterpret_cast<const uint2*>(bufc);   // [plane][4096 uint2]
        const float* ens = reinterpret_cast<const float*>(bufc + 65536);

        float acc[4][4][4];
        #pragma unroll
        for (int mt = 0; mt < 4; mt++)
            #pragma unroll
            for (int nt = 0; nt < 4; nt++)
                #pragma unroll
                for (int q = 0; q < 4; q++) acc[mt][nt][q] = 0.0f;

        #pragma unroll
        for (int s = 0; s < 8; s++) {
            uint4 a[2][4];
            uint2 b[2][4];
            #pragma unroll
            for (int p = 0; p < 2; p++) {
                #pragma unroll
                for (int mt = 0; mt < 4; mt++)
                    a[p][mt] = Af[p * 2048 + ((mg * 8 + s) * 4 + mt) * 32 + lane];
                #pragma unroll
                for (int nt = 0; nt < 4; nt++)
                    b[p][nt] = Bf[p * 4096 + ((ng * 8 + s) * 4 + nt) * 32 + lane];
            }
            // pass-major order: same-accumulator MMAs are 16 instructions apart
            #pragma unroll
            for (int mt = 0; mt < 4; mt++)
                #pragma unroll
                for (int nt = 0; nt < 4; nt++)
                    MMA(acc[mt][nt], a[0][mt], b[0][nt]);   // h1*e1
            #pragma unroll
            for (int mt = 0; mt < 4; mt++)
                #pragma unroll
                for (int nt = 0; nt < 4; nt++)
                    MMA(acc[mt][nt], a[0][mt], b[1][nt]);   // h1*e2
            #pragma unroll
            for (int mt = 0; mt < 4; mt++)
                #pragma unroll
                for (int nt = 0; nt < 4; nt++)
                    MMA(acc[mt][nt], a[1][mt], b[0][nt]);   // h2*e1
        }

        // --- fold tile into running argmax (codes ascending => first-max) ---
        #pragma unroll
        for (int nt = 0; nt < 4; nt++) {
            int cl = ng * 32 + nt * 8 + (lane & 3) * 2;
            float e0 = ens[cl], e1 = ens[cl + 1];
            int code0 = t * TN + cl;
            #pragma unroll
            for (int mt = 0; mt < 4; mt++) {
                int i0 = mt * 2, i1 = mt * 2 + 1;
                float d;
                d = acc[mt][nt][0] - e0;
                if (d > best[i0]) { best[i0] = d; bestk[i0] = code0; }
                d = acc[mt][nt][1] - e1;
                if (d > best[i0]) { best[i0] = d; bestk[i0] = code0 + 1; }
                d = acc[mt][nt][2] - e0;
                if (d > best[i1]) { best[i1] = d; bestk[i1] = code0; }
                d = acc[mt][nt][3] - e1;
                if (d > best[i1]) { best[i1] = d; bestk[i1] = code0 + 1; }
            }
        }
    }

    // --- reduce over the 4 col-lanes sharing each row ---
    #pragma unroll
    for (int off = 1; off <= 2; off <<= 1) {
        #pragma unroll
        for (int i = 0; i < 8; i++) {
            float ov = __shfl_xor_sync(0xffffffffu, best[i], off);
            int   ok = __shfl_xor_sync(0xffffffffu, bestk[i], off);
            if (ov > best[i] || (ov == best[i] && ok < bestk[i])) {
                best[i] = ov; bestk[i] = ok;
            }
        }
    }
    if ((lane & 3) == 0) {
        #pragma unroll
        for (int i = 0; i < 8; i++) {
            int R = mg * 64 + (i >> 1) * 16 + (i & 1) * 8 + (lane >> 2);
            redV[R * 4 + ng] = best[i];
            redK[R * 4 + ng] = bestk[i];
        }
    }
    __syncthreads();
    if (tid < TM) {
        float bv = redV[tid * 4];
        int   bk = redK[tid * 4];
        #pragma unroll
        for (int j = 1; j < 4; j++) {
            float v  = redV[tid * 4 + j];
            int   k2 = redK[tid * 4 + j];
            if (v > bv || (v == bv && k2 < bk)) { bv = v; bk = k2; }
        }
        sidx[tid] = bk;
        outind[tok0 + tid] = (float)bk;
        atomicAdd(&g_counts[bk], 1.0f);
    }
    __syncthreads();

    // --- fused epilogue: quantized gather + EMA scatter-adds ---
    for (int i = tid; i < TM * 32; i += 256) {
        int tt = i >> 5;
        int d4 = i & 31;
        int k  = sidx[tt];
        float4 ev = *reinterpret_cast<const float4*>(embed + (size_t)k * Dm + d4 * 4);
        *reinterpret_cast<float4*>(outq + (size_t)(tok0 + tt) * Dm + d4 * 4) = ev;
        float4 xv = *reinterpret_cast<const float4*>(x + (size_t)(tok0 + tt) * Dm + d4 * 4);
        float* es = g_esum + (size_t)k * Dm + d4 * 4;
        atomicAdd(es + 0, xv.x);
        atomicAdd(es + 1, xv.y);
        atomicAdd(es + 2, xv.z);
        atomicAdd(es + 3, xv.w);
    }
}

// ------------------------------------------------------------------
// finalize A: cluster-size EMA + laplace smoothing (1 block, K threads)
// ------------------------------------------------------------------
__global__ void __launch_bounds__(1024)
finalize_a(const float* __restrict__ cluster_size, float* __restrict__ out_ncs)
{
    __shared__ float ssum[32];
    __shared__ float s_total;
    int tid = threadIdx.x, lane = tid & 31;

    float ncs = cluster_size[tid] * DECAYF + OMDEC * g_counts[tid];
    out_ncs[tid] = ncs;

    float s = ncs;
    #pragma unroll
    for (int o = 16; o > 0; o >>= 1) s += __shfl_xor_sync(0xffffffffu, s, o);
    if (lane == 0) ssum[tid >> 5] = s;
    __syncthreads();
    if (tid < 32) {
        float v = ssum[tid];
        #pragma unroll
        for (int o = 16; o > 0; o >>= 1) v += __shfl_xor_sync(0xffffffffu, v, o);
        if (tid == 0) s_total = v;
    }
    __syncthreads();
    float total = s_total;
    g_smooth[tid] = (ncs + EPSV) / (total + (float)Kc * EPSV) * total;
}

// ------------------------------------------------------------------
// finalize B: embed_avg EMA + normalized embed (wide grid)
// ------------------------------------------------------------------
__global__ void finalize_b(const float* __restrict__ embed_avg,
                           float* __restrict__ out_ne,
                           float* __restrict__ out_nea)
{
    int i = blockIdx.x * blockDim.x + threadIdx.x;
    if (i >= Kc * Dm) return;
    float nea = embed_avg[i] * DECAYF + OMDEC * g_esum[i];
    out_nea[i] = nea;
    out_ne[i]  = nea / g_smooth[i >> 7];
}

// ------------------------------------------------------------------
// launch
// inputs: 0=x [N,128], 1=embed [1024,128], 2=embed_avg [1024,128],
//         3=cluster_size [1024]  (all f32)
// output (concat f32): quantized [N*128] | embed_ind [N] | new_embed [K*128]
//                    | new_cluster_size [K] | new_embed_avg [K*128]
// ------------------------------------------------------------------
extern "C" void kernel_launch(void* const* d_in, const int* in_sizes, int n_in,
                              void* d_out, int out_size)
{
    const float* x     = (const float*)d_in[0];
    const float* embed = (const float*)d_in[1];
    const float* eavg  = (const float*)d_in[2];
    const float* csz   = (const float*)d_in[3];
    float* out = (float*)d_out;

    int N = in_sizes[0] / Dm;

    size_t o_ind = (size_t)N * Dm;
    size_t o_ne  = o_ind + N;
    size_t o_ncs = o_ne + (size_t)Kc * Dm;
    size_t o_nea = o_ncs + Kc;

    cudaFuncSetAttribute(argmax_kernel,
                         cudaFuncAttributeMaxDynamicSharedMemorySize, SMEM_TOTAL);

    init_kernel<<<(Kc * Dm + 255) / 256, 256>>>();
    enorm_kernel<<<(Kc * 32 + 255) / 256, 256>>>(embed);
    prep_e_kernel<<<(Kc * 64 + 255) / 256, 256>>>(embed);
    argmax_kernel<<<N / TM, 256, SMEM_TOTAL>>>(x, embed, out, out + o_ind);
    finalize_a<<<1, 1024>>>(csz, out + o_ncs);
    finalize_b<<<(Kc * Dm + 255) / 256, 256>>>(eavg, out + o_ne, out + o_nea);
}